// round 4
// baseline (speedup 1.0000x reference)
#include <cuda_runtime.h>

#define HH 512
#define WW 1024
#define DD 32
#define HWSZ (HH*WW)

// Packed RGBA (A unused) copies of the two source views. 16 MB static scratch.
__device__ float4 g_img[2][HWSZ];

__global__ void pack_kernel(const float* __restrict__ ref, const float* __restrict__ inp) {
    int i = blockIdx.x * blockDim.x + threadIdx.x;
    if (i >= HWSZ) return;
    g_img[0][i] = make_float4(ref[i], ref[i + HWSZ], ref[i + 2 * HWSZ], 0.f);
    g_img[1][i] = make_float4(inp[i], inp[i + HWSZ], inp[i + 2 * HWSZ], 0.f);
}

// Exact f32 constants as the reference's fp32 trace sees them.
#define ANGC   0.006135923151542565f    // f32(2*pi/1024) == f32(pi/512)
#define SCALEF 162.97466172610083f      // f32(W/(2*pi)) == f32(H/pi)
#define TWOPIF 6.283185307179586f       // f32(2*pi)
#define PIF    3.141592653589793f       // f32(pi)

struct VRT { float r00,r01,r02,r10,r11,r12,r20,r21,r22,tx,ty,tz; };

__device__ __forceinline__ float3 bisample(const float4* __restrict__ im, float gx, float gy) {
    int ix = __float2int_rd(gx);
    int iy = __float2int_rd(gy);
    float wx = gx - (float)ix;
    float wy = gy - (float)iy;
    int x0 = ix & (WW - 1);
    int x1 = (ix + 1) & (WW - 1);          // wrap in x (W power of two)
    int y0 = min(max(iy, 0), HH - 1);      // clamp in y
    int y1 = min(y0 + 1, HH - 1);
    const float4* r0p = im + y0 * WW;
    const float4* r1p = im + y1 * WW;
    float4 a = __ldg(r0p + x0);
    float4 b = __ldg(r0p + x1);
    float4 c = __ldg(r1p + x0);
    float4 d = __ldg(r1p + x1);
    float t0x = fmaf(wx, b.x - a.x, a.x);
    float t0y = fmaf(wx, b.y - a.y, a.y);
    float t0z = fmaf(wx, b.z - a.z, a.z);
    float b0x = fmaf(wx, d.x - c.x, c.x);
    float b0y = fmaf(wx, d.y - c.y, c.y);
    float b0z = fmaf(wx, d.z - c.z, c.z);
    float3 o;
    o.x = fmaf(wy, b0x - t0x, t0x);
    o.y = fmaf(wy, b0y - t0y, t0y);
    o.z = fmaf(wy, b0z - t0z, t0z);
    return o;
}

__global__ void __launch_bounds__(256)
warp_kernel(const float* __restrict__ R0, const float* __restrict__ t0,
            const float* __restrict__ R1, const float* __restrict__ t1,
            const float* __restrict__ radii, float* __restrict__ out) {
    __shared__ float s_r[DD];
    int tid = threadIdx.x;
    if (tid < DD) s_r[tid] = __ldg(radii + tid);
    __syncthreads();

    int idx = blockIdx.x * blockDim.x + tid;
    int h = idx >> 10;
    int w = idx & (WW - 1);

    // Pixel-center angles: (i + 0.5) * f32(2pi/W), bit-matching the reference.
    float theta = __fmul_rn((float)w + 0.5f, ANGC);
    float phi   = __fmul_rn((float)h + 0.5f, ANGC);
    // libdevice sinf/cosf == XLA's __nv_sinf/__nv_cosf: bit-identical.
    float st = sinf(theta), ct = cosf(theta);
    float sp = sinf(phi),   cp = cosf(phi);
    float dx = __fmul_rn(sp, ct);
    float dy = __fmul_rn(sp, st);
    float dz = cp;

    VRT vc[2];
#pragma unroll
    for (int v = 0; v < 2; v++) {
        const float* R = v ? R1 : R0;
        const float* t = v ? t1 : t0;
        VRT& c = vc[v];
        c.r00 = __ldg(R + 0); c.r01 = __ldg(R + 1); c.r02 = __ldg(R + 2);
        c.r10 = __ldg(R + 3); c.r11 = __ldg(R + 4); c.r12 = __ldg(R + 5);
        c.r20 = __ldg(R + 6); c.r21 = __ldg(R + 7); c.r22 = __ldg(R + 8);
        c.tx = __ldg(t + 0);  c.ty = __ldg(t + 1);  c.tz = __ldg(t + 2);
    }

    for (int d = 0; d < DD; d++) {
        float r = s_r[d];
        // pts = radii * dirs (reference scales the direction FIRST)
        float rx = __fmul_rn(r, dx);
        float ry = __fmul_rn(r, dy);
        float rz = __fmul_rn(r, dz);
        float* op = out + (size_t)d * (6 * HWSZ) + idx;
#pragma unroll
        for (int v = 0; v < 2; v++) {
            VRT& c = vc[v];
            // einsum row-dot, cuBLAS-style k-ascending fma chain
            // (acc starts at 0: fma(a0,b0,0) == mul.rn), then separate +t add.
            float px = __fadd_rn(fmaf(c.r02, rz, fmaf(c.r01, ry, __fmul_rn(c.r00, rx))), c.tx);
            float py = __fadd_rn(fmaf(c.r12, rz, fmaf(c.r11, ry, __fmul_rn(c.r10, rx))), c.ty);
            float pz = __fadd_rn(fmaf(c.r22, rz, fmaf(c.r21, ry, __fmul_rn(c.r20, rx))), c.tz);
            // norm^2: XLA reduce of x*x, sequential, no fma contraction.
            float s = __fadd_rn(__fadd_rn(__fmul_rn(px, px), __fmul_rn(py, py)),
                                __fmul_rn(pz, pz));
            // n_z = pz / sqrt(s): IEEE sqrt.rn + div.rn (XLA default lowering).
            float nz = __fdiv_rn(pz, __fsqrt_rn(s));
            nz = fminf(fmaxf(nz, -1.0f), 1.0f);
            // JAX acos decomposition: 2*atan2(sqrt(1 - x*x), 1 + x), x==-1 -> pi.
            float ph;
            if (nz != -1.0f) {
                float xx = __fmul_rn(nz, nz);
                float yy = __fsqrt_rn(__fadd_rn(1.0f, -xx));
                ph = 2.0f * atan2f(yy, __fadd_rn(1.0f, nz));
            } else {
                ph = PIF;
            }
            // theta = mod(atan2(py, px), 2pi): atan2 is scale-invariant so the
            // normalize division cancels; for x in (-2pi,0) XLA's mod = x + 2pi.
            float th = atan2f(py, px);
            if (th < 0.0f) th = __fadd_rn(th, TWOPIF);
            float gx = __fadd_rn(__fmul_rn(th, SCALEF), -0.5f);
            float gy = __fadd_rn(__fmul_rn(ph, SCALEF), -0.5f);

            float3 smp = bisample(g_img[v], gx, gy);
            op[(v * 3 + 0) * HWSZ] = smp.x;
            op[(v * 3 + 1) * HWSZ] = smp.y;
            op[(v * 3 + 2) * HWSZ] = smp.z;
        }
    }
}

extern "C" void kernel_launch(void* const* d_in, const int* in_sizes, int n_in,
                              void* d_out, int out_size) {
    const float* view_ref = (const float*)d_in[0];
    const float* view_inp = (const float*)d_in[1];
    const float* R0 = (const float*)d_in[2];
    const float* t0 = (const float*)d_in[3];
    const float* R1 = (const float*)d_in[4];
    const float* t1 = (const float*)d_in[5];
    const float* radii = (const float*)d_in[6];
    float* out = (float*)d_out;

    pack_kernel<<<(HWSZ + 255) / 256, 256>>>(view_ref, view_inp);
    warp_kernel<<<(HWSZ + 255) / 256, 256>>>(R0, t0, R1, t1, radii, out);
}

// round 5
// speedup vs baseline: 1.0389x; 1.0389x over previous
#include <cuda_runtime.h>

#define HH 512
#define WW 1024
#define DD 32
#define HWSZ (HH*WW)

// Packed RGBA (A unused) copies of the two source views. 16 MB static scratch.
__device__ float4 g_img[2][HWSZ];

__global__ void pack_kernel(const float* __restrict__ ref, const float* __restrict__ inp) {
    int i = blockIdx.x * blockDim.x + threadIdx.x;
    if (i >= HWSZ) return;
    g_img[0][i] = make_float4(ref[i], ref[i + HWSZ], ref[i + 2 * HWSZ], 0.f);
    g_img[1][i] = make_float4(inp[i], inp[i + HWSZ], inp[i + 2 * HWSZ], 0.f);
}

// Exact f32 constants as the reference's fp32 trace sees them.
#define ANGC   0.006135923151542565f    // f32(2*pi/1024) == f32(pi/512)
#define SCALEF 162.97466172610083f      // f32(W/(2*pi)) == f32(H/pi)
#define TWOPIF 6.283185307179586f       // f32(2*pi)
#define PIF    3.141592653589793f       // f32(pi)

__device__ __forceinline__ float3 bisample(const float4* __restrict__ im, float gx, float gy) {
    int ix = __float2int_rd(gx);
    int iy = __float2int_rd(gy);
    float wx = gx - (float)ix;
    float wy = gy - (float)iy;
    int x0 = ix & (WW - 1);
    int x1 = (ix + 1) & (WW - 1);          // wrap in x (W power of two)
    int y0 = min(max(iy, 0), HH - 1);      // clamp in y
    int y1 = min(y0 + 1, HH - 1);
    const float4* r0p = im + (y0 << 10);
    const float4* r1p = im + (y1 << 10);
    float4 a = __ldg(r0p + x0);
    float4 b = __ldg(r0p + x1);
    float4 c = __ldg(r1p + x0);
    float4 d = __ldg(r1p + x1);
    float t0x = fmaf(wx, b.x - a.x, a.x);
    float t0y = fmaf(wx, b.y - a.y, a.y);
    float t0z = fmaf(wx, b.z - a.z, a.z);
    float b0x = fmaf(wx, d.x - c.x, c.x);
    float b0y = fmaf(wx, d.y - c.y, c.y);
    float b0z = fmaf(wx, d.z - c.z, c.z);
    float3 o;
    o.x = fmaf(wy, b0x - t0x, t0x);
    o.y = fmaf(wy, b0y - t0y, t0y);
    o.z = fmaf(wy, b0z - t0z, t0z);
    return o;
}

// One block = one (pixel-tile, view). blockIdx.y selects the view, halving
// per-thread live state (one R/t, one compute chain) -> higher occupancy.
__global__ void __launch_bounds__(256, 6)
warp_kernel(const float* __restrict__ R0, const float* __restrict__ t0,
            const float* __restrict__ R1, const float* __restrict__ t1,
            const float* __restrict__ radii, float* __restrict__ out) {
    __shared__ float s_r[DD];
    int tid = threadIdx.x;
    if (tid < DD) s_r[tid] = __ldg(radii + tid);
    __syncthreads();

    int v = blockIdx.y;
    int idx = blockIdx.x * blockDim.x + tid;
    int h = idx >> 10;
    int w = idx & (WW - 1);

    // Pixel-center angles: (i + 0.5) * f32(2pi/W), bit-matching the reference.
    float theta = __fmul_rn((float)w + 0.5f, ANGC);
    float phi   = __fmul_rn((float)h + 0.5f, ANGC);
    float st = sinf(theta), ct = cosf(theta);
    float sp = sinf(phi),   cp = cosf(phi);
    float dx = __fmul_rn(sp, ct);
    float dy = __fmul_rn(sp, st);
    float dz = cp;

    const float* R = v ? R1 : R0;
    const float* t = v ? t1 : t0;
    float r00 = __ldg(R + 0), r01 = __ldg(R + 1), r02 = __ldg(R + 2);
    float r10 = __ldg(R + 3), r11 = __ldg(R + 4), r12 = __ldg(R + 5);
    float r20 = __ldg(R + 6), r21 = __ldg(R + 7), r22 = __ldg(R + 8);
    float tx = __ldg(t + 0),  ty = __ldg(t + 1),  tz = __ldg(t + 2);

    const float4* im = g_img[v];
    float* ob = out + (size_t)(v * 3) * HWSZ + idx;

#pragma unroll 2
    for (int d = 0; d < DD; d++) {
        float r = s_r[d];
        // pts = radii * dirs (reference scales the direction FIRST)
        float rx = __fmul_rn(r, dx);
        float ry = __fmul_rn(r, dy);
        float rz = __fmul_rn(r, dz);
        // einsum row-dot, k-ascending fma chain (acc init 0 -> first term is
        // a plain mul.rn), then separate +t add. Bit-matches the reference.
        float px = __fadd_rn(fmaf(r02, rz, fmaf(r01, ry, __fmul_rn(r00, rx))), tx);
        float py = __fadd_rn(fmaf(r12, rz, fmaf(r11, ry, __fmul_rn(r10, rx))), ty);
        float pz = __fadd_rn(fmaf(r22, rz, fmaf(r21, ry, __fmul_rn(r20, rx))), tz);
        // norm^2: sequential reduce of squares, no fma contraction.
        float s = __fadd_rn(__fadd_rn(__fmul_rn(px, px), __fmul_rn(py, py)),
                            __fmul_rn(pz, pz));
        // n_z = pz / sqrt(s): IEEE sqrt.rn + div.rn.
        float nz = __fdiv_rn(pz, __fsqrt_rn(s));
        nz = fminf(fmaxf(nz, -1.0f), 1.0f);
        // JAX acos decomposition: 2*atan2(sqrt(1 - x*x), 1 + x), x==-1 -> pi.
        float ph;
        if (nz != -1.0f) {
            float xx = __fmul_rn(nz, nz);
            float yy = __fsqrt_rn(__fadd_rn(1.0f, -xx));
            ph = 2.0f * atan2f(yy, __fadd_rn(1.0f, nz));
        } else {
            ph = PIF;
        }
        // theta = mod(atan2(py, px), 2pi); atan2 scale-invariance cancels the
        // normalize division; for x in (-2pi, 0) XLA's mod = x + 2pi.
        float th = atan2f(py, px);
        if (th < 0.0f) th = __fadd_rn(th, TWOPIF);
        float gx = __fadd_rn(__fmul_rn(th, SCALEF), -0.5f);
        float gy = __fadd_rn(__fmul_rn(ph, SCALEF), -0.5f);

        float3 smp = bisample(im, gx, gy);
        float* op = ob + (size_t)d * (6 * HWSZ);
        op[0 * HWSZ] = smp.x;
        op[1 * HWSZ] = smp.y;
        op[2 * HWSZ] = smp.z;
    }
}

extern "C" void kernel_launch(void* const* d_in, const int* in_sizes, int n_in,
                              void* d_out, int out_size) {
    const float* view_ref = (const float*)d_in[0];
    const float* view_inp = (const float*)d_in[1];
    const float* R0 = (const float*)d_in[2];
    const float* t0 = (const float*)d_in[3];
    const float* R1 = (const float*)d_in[4];
    const float* t1 = (const float*)d_in[5];
    const float* radii = (const float*)d_in[6];
    float* out = (float*)d_out;

    pack_kernel<<<(HWSZ + 255) / 256, 256>>>(view_ref, view_inp);
    dim3 grid((HWSZ + 255) / 256, 2);
    warp_kernel<<<grid, 256>>>(R0, t0, R1, t1, radii, out);
}